// round 11
// baseline (speedup 1.0000x reference)
#include <cuda_runtime.h>

#define NT 512

__device__ __forceinline__ int reflect512(int i) {
    i = (i < 0) ? -i : i;
    return (i > 511) ? 1022 - i : i;
}
__device__ __forceinline__ int clamp511(int i) {
    return min(max(i, 0), 511);
}
__device__ __forceinline__ float grayf(const float* __restrict__ base, int off) {
    float r = base[off], g = base[off + 262144], b = base[off + 524288];
    return fmaf(0.1495f, r, fmaf(0.2935f, g, fmaf(0.057f, b, 0.5f)));
}
__device__ __forceinline__ int octclass(float gx, float gy) {
    const float T = 0.41421356237309503f;  // tan(22.5 deg)
    float ax = fabsf(gx), ay = fabsf(gy);
    if (ay <= T * ax) return 0;
    if (ax <= T * ay) return 2;
    return ((__float_as_int(gx) ^ __float_as_int(gy)) >= 0) ? 1 : 3;
}
// sqrt without MUFU: bit-hack rsqrt + 2 Newton iterations. x >= 1e-6 always.
__device__ __forceinline__ float fast_sqrt(float x) {
    float y = __int_as_float(0x5f3759df - (__float_as_int(x) >> 1));
    y = y * fmaf(-0.5f * x, y * y, 1.5f);
    y = y * fmaf(-0.5f * x, y * y, 1.5f);
    return x * y;
}
__device__ __forceinline__ float4 hblur4(float4 v0, float4 v1,
                                         float w0, float w1, float w2) {
    float4 o;
    o.x = w0 * (v0.x + v1.x) + w1 * (v0.y + v0.w) + w2 * v0.z;
    o.y = w0 * (v0.y + v1.y) + w1 * (v0.z + v1.x) + w2 * v0.w;
    o.z = w0 * (v0.z + v1.z) + w1 * (v0.w + v1.y) + w2 * v1.x;
    o.w = w0 * (v0.w + v1.w) + w1 * (v1.x + v1.z) + w2 * v1.y;
    return o;
}

struct Row6 { float m, x, y, z, w, p; };

__device__ __forceinline__ void sobel_row(const Row6& a, const Row6& b, const Row6& c,
                                          float4& mg, uchar4& cc) {
    {
        float gx = (a.y - a.m) + 2.0f * (b.y - b.m) + (c.y - c.m);
        float gy = (c.m - a.m) + 2.0f * (c.x - a.x) + (c.y - a.y);
        mg.x = fmaf(gx, gx, fmaf(gy, gy, 1e-6f)); cc.x = (unsigned char)octclass(gx, gy);
    }
    {
        float gx = (a.z - a.x) + 2.0f * (b.z - b.x) + (c.z - c.x);
        float gy = (c.x - a.x) + 2.0f * (c.y - a.y) + (c.z - a.z);
        mg.y = fmaf(gx, gx, fmaf(gy, gy, 1e-6f)); cc.y = (unsigned char)octclass(gx, gy);
    }
    {
        float gx = (a.w - a.y) + 2.0f * (b.w - b.y) + (c.w - c.y);
        float gy = (c.y - a.y) + 2.0f * (c.z - a.z) + (c.w - a.w);
        mg.z = fmaf(gx, gx, fmaf(gy, gy, 1e-6f)); cc.z = (unsigned char)octclass(gx, gy);
    }
    {
        float gx = (a.p - a.z) + 2.0f * (b.p - b.z) + (c.p - c.z);
        float gy = (c.z - a.z) + 2.0f * (c.w - a.w) + (c.p - a.p);
        mg.w = fmaf(gx, gx, fmaf(gy, gy, 1e-6f)); cc.w = (unsigned char)octclass(gx, gy);
    }
}

__global__ __launch_bounds__(NT)
void canny_fused_kernel(const float* __restrict__ in, float* __restrict__ out)
{
    // 64x64 output tile. Row stride 72 floats (rows 16B aligned).
    //   poolA: sg[72][72] (gray, cols 0..71) -> sb[68][72] (vblur, cols 0..67)
    //   poolB: th[72][72] (hblur, cols 0..67) -> smg[66][72] (squared mag, cols 1..66)
    __shared__ __align__(16) float poolA[72 * 72];
    __shared__ __align__(16) float poolB[72 * 72];
    __shared__ __align__(16) unsigned char sclbuf[66 * 72];

    float (*sg)[72]  = reinterpret_cast<float(*)[72]>(poolA);
    float (*sb)[72]  = reinterpret_cast<float(*)[72]>(poolA);
    float (*th)[72]  = reinterpret_cast<float(*)[72]>(poolB);
    float (*smg)[72] = reinterpret_cast<float(*)[72]>(poolB);
    unsigned char (*scl)[72] = reinterpret_cast<unsigned char(*)[72]>(sclbuf);

    const int tid = threadIdx.x;
    const int bx0 = blockIdx.x * 64, by0 = blockIdx.y * 64;
    const float* base = in + (size_t)blockIdx.z * 786432u;
    const float w0 = 0.054488685f, w1 = 0.24420134f, w2 = 0.40261995f;

    const bool reflX = (blockIdx.x == 0u) | (blockIdx.x == 7u);
    const bool reflY = (blockIdx.y == 0u) | (blockIdx.y == 7u);

    // ---- stage 1: gray 72 rows x 72 cols; 36 row-pairs x 18 groups = 648 items ----
    if (!(reflX | reflY)) {
        #pragma unroll
        for (int k = 0; k < 2; k++) {
            int u = tid + k * NT;
            if (u < 648) {
                int pr = u / 18, g = u - pr * 18;
                int ly = 2 * pr;
                int off = (by0 - 4 + ly) * 512 + (bx0 - 4) + 4 * g;
                #pragma unroll
                for (int rr = 0; rr < 2; rr++) {
                    float4 r  = *(const float4*)(base + off);
                    float4 gg = *(const float4*)(base + off + 262144);
                    float4 bb = *(const float4*)(base + off + 524288);
                    float4 o;
                    o.x = fmaf(0.1495f, r.x, fmaf(0.2935f, gg.x, fmaf(0.057f, bb.x, 0.5f)));
                    o.y = fmaf(0.1495f, r.y, fmaf(0.2935f, gg.y, fmaf(0.057f, bb.y, 0.5f)));
                    o.z = fmaf(0.1495f, r.z, fmaf(0.2935f, gg.z, fmaf(0.057f, bb.z, 0.5f)));
                    o.w = fmaf(0.1495f, r.w, fmaf(0.2935f, gg.w, fmaf(0.057f, bb.w, 0.5f)));
                    *(float4*)&sg[ly + rr][4 * g] = o;
                    off += 512;
                }
            }
        }
    } else {
        for (int u = tid; u < 72 * 72; u += NT) {
            int ly = u / 72, lx = u - ly * 72;
            int ay = by0 - 4 + ly, ax = bx0 - 4 + lx;
            float g = 0.0f;
            if ((unsigned)ay < 512u && (unsigned)ax < 512u) g = grayf(base, ay * 512 + ax);
            sg[ly][lx] = g;
        }
    }
    __syncthreads();

    // ---- stage 2: horizontal blur -> th cols 0..67; 36 row-pairs x 17 groups = 612 items ----
    if (!reflX) {
        #pragma unroll
        for (int k = 0; k < 2; k++) {
            int u = tid + k * NT;
            if (u < 612) {
                int pr = u / 17, g = u - pr * 17;
                int ly = 2 * pr;
                float4 a0 = *(const float4*)&sg[ly][4 * g];
                float4 a1 = *(const float4*)&sg[ly][4 * g + 4];
                float4 b0 = *(const float4*)&sg[ly + 1][4 * g];
                float4 b1 = *(const float4*)&sg[ly + 1][4 * g + 4];
                *(float4*)&th[ly][4 * g]     = hblur4(a0, a1, w0, w1, w2);
                *(float4*)&th[ly + 1][4 * g] = hblur4(b0, b1, w0, w1, w2);
            }
        }
    } else {
        const int ox = bx0 - 4;
        for (int u = tid; u < 72 * 68; u += NT) {
            int ly = u / 68, j = u - ly * 68;
            int cx = clamp511(bx0 - 2 + j);
            th[ly][j] = w0 * (sg[ly][reflect512(cx - 2) - ox] + sg[ly][reflect512(cx + 2) - ox])
                      + w1 * (sg[ly][reflect512(cx - 1) - ox] + sg[ly][reflect512(cx + 1) - ox])
                      + w2 * sg[ly][reflect512(cx) - ox];
        }
    }
    __syncthreads();

    // ---- stage 3: vertical blur -> sb rows 0..67; 34 row-pairs x 17 groups = 578 items ----
    #pragma unroll
    for (int k = 0; k < 2; k++) {
        int u = tid + k * NT;
        if (u < 578) {
            int pr = u / 17, g = u - pr * 17;
            int i = 2 * pr;
            if (!reflY) {
                float4 a = *(const float4*)&th[i    ][4 * g];
                float4 b = *(const float4*)&th[i + 1][4 * g];
                float4 c = *(const float4*)&th[i + 2][4 * g];
                float4 d = *(const float4*)&th[i + 3][4 * g];
                float4 e = *(const float4*)&th[i + 4][4 * g];
                float4 f = *(const float4*)&th[i + 5][4 * g];
                float4 o0, o1;
                o0.x = w0 * (a.x + e.x) + w1 * (b.x + d.x) + w2 * c.x;
                o0.y = w0 * (a.y + e.y) + w1 * (b.y + d.y) + w2 * c.y;
                o0.z = w0 * (a.z + e.z) + w1 * (b.z + d.z) + w2 * c.z;
                o0.w = w0 * (a.w + e.w) + w1 * (b.w + d.w) + w2 * c.w;
                o1.x = w0 * (b.x + f.x) + w1 * (c.x + e.x) + w2 * d.x;
                o1.y = w0 * (b.y + f.y) + w1 * (c.y + e.y) + w2 * d.y;
                o1.z = w0 * (b.z + f.z) + w1 * (c.z + e.z) + w2 * d.z;
                o1.w = w0 * (b.w + f.w) + w1 * (c.w + e.w) + w2 * d.w;
                *(float4*)&sb[i][4 * g]     = o0;
                *(float4*)&sb[i + 1][4 * g] = o1;
            } else {
                #pragma unroll
                for (int rr = 0; rr < 2; rr++) {
                    int ir = i + rr;
                    int cy = clamp511(by0 - 2 + ir), oy = by0 - 4;
                    int r0 = reflect512(cy - 2) - oy, r1 = reflect512(cy - 1) - oy;
                    int r2 = reflect512(cy) - oy;
                    int r3 = reflect512(cy + 1) - oy, r4 = reflect512(cy + 2) - oy;
                    float4 a = *(const float4*)&th[r0][4 * g];
                    float4 b = *(const float4*)&th[r1][4 * g];
                    float4 c = *(const float4*)&th[r2][4 * g];
                    float4 d = *(const float4*)&th[r3][4 * g];
                    float4 e = *(const float4*)&th[r4][4 * g];
                    float4 o;
                    o.x = w0 * (a.x + e.x) + w1 * (b.x + d.x) + w2 * c.x;
                    o.y = w0 * (a.y + e.y) + w1 * (b.y + d.y) + w2 * c.y;
                    o.z = w0 * (a.z + e.z) + w1 * (b.z + d.z) + w2 * c.z;
                    o.w = w0 * (a.w + e.w) + w1 * (b.w + d.w) + w2 * c.w;
                    *(float4*)&sb[ir][4 * g] = o;
                }
            }
        }
    }
    __syncthreads();

    // ---- stage 4: Sobel + squared mag + class -> smg rows 0..65; 33 pairs x 17 = 561 items ----
    #pragma unroll
    for (int k = 0; k < 2; k++) {
        int u = tid + k * NT;
        if (u < 561) {
            int pr = u / 17, g = u - pr * 17;
            int i = 2 * pr;
            int cm = max(4 * g - 1, 0);
            Row6 r[4];
            #pragma unroll
            for (int rr = 0; rr < 4; rr++) {
                const float* row = &sb[i + rr][0];
                float4 v = *(const float4*)&row[4 * g];
                r[rr].m = row[cm]; r[rr].x = v.x; r[rr].y = v.y;
                r[rr].z = v.z;     r[rr].w = v.w; r[rr].p = row[4 * g + 4];
            }
            float4 mgA, mgB; uchar4 ccA, ccB;
            sobel_row(r[0], r[1], r[2], mgA, ccA);
            sobel_row(r[1], r[2], r[3], mgB, ccB);
            *(float4*)&smg[i][4 * g]     = mgA;
            *(uchar4*)&scl[i][4 * g]     = ccA;
            *(float4*)&smg[i + 1][4 * g] = mgB;
            *(uchar4*)&scl[i + 1][4 * g] = ccB;
        }
    }
    __syncthreads();

    // ---- stage 5: NMS on squared magnitudes + fast_sqrt; 64 rows x 16 groups = 1024 items ----
    const unsigned DY = 0x0001u, DX = 0x0122u;
    const bool border = reflX | reflY;

    #pragma unroll
    for (int k = 0; k < 2; k++) {
        int u = tid + k * NT;
        int iy = u >> 4, g = u & 15;
        int ii = iy + 1;
        int j0 = 4 * g + 2;

        float2 ca = *(const float2*)&smg[ii][j0];
        float2 cb = *(const float2*)&smg[ii][j0 + 2];
        uchar2 ka = *(const uchar2*)&scl[ii][j0];
        uchar2 kb = *(const uchar2*)&scl[ii][j0 + 2];
        float mcv[4] = {ca.x, ca.y, cb.x, cb.y};
        int   cls[4] = {ka.x, ka.y, kb.x, kb.y};

        float4 res;
        float* rp = &res.x;
        #pragma unroll
        for (int t = 0; t < 4; t++) {
            int s  = cls[t] * 4;
            int dy = (int)((DY >> s) & 0xFu) - 1;
            int dx = (int)((DX >> s) & 0xFu) - 1;
            int jj = j0 + t;
            float mp = smg[ii + dy][jj + dx];
            float mq = smg[ii - dy][jj - dx];
            if (border) {
                int ay = by0 + iy, ax = bx0 + 4 * g + t;
                if (!((unsigned)(ay + dy) < 512u && (unsigned)(ax + dx) < 512u)) mp = 0.0f;
                if (!((unsigned)(ay - dy) < 512u && (unsigned)(ax - dx) < 512u)) mq = 0.0f;
            }
            float m = mcv[t];
            rp[t] = (m > mp && m > mq) ? fast_sqrt(m) : 0.0f;
        }
        *(float4*)&out[((size_t)blockIdx.z * 512 + by0 + iy) * 512 + bx0 + 4 * g] = res;
    }
}

extern "C" void kernel_launch(void* const* d_in, const int* in_sizes, int n_in,
                              void* d_out, int out_size)
{
    (void)in_sizes; (void)n_in; (void)out_size;
    const float* data = (const float*)d_in[0];
    float* out = (float*)d_out;

    dim3 grid(8, 8, 16);
    dim3 block(NT);
    canny_fused_kernel<<<grid, block>>>(data, out);
}

// round 12
// speedup vs baseline: 1.0110x; 1.0110x over previous
#include <cuda_runtime.h>

#define NT 256

__device__ __forceinline__ int reflect512(int i) {
    i = (i < 0) ? -i : i;
    return (i > 511) ? 1022 - i : i;
}
__device__ __forceinline__ int clamp511(int i) {
    return min(max(i, 0), 511);
}
__device__ __forceinline__ float grayf(const float* __restrict__ base, int off) {
    float r = base[off], g = base[off + 262144], b = base[off + 524288];
    return fmaf(0.1495f, r, fmaf(0.2935f, g, fmaf(0.057f, b, 0.5f)));
}
__device__ __forceinline__ int octclass(float gx, float gy) {
    const float T = 0.41421356237309503f;  // tan(22.5 deg)
    float ax = fabsf(gx), ay = fabsf(gy);
    if (ay <= T * ax) return 0;
    if (ax <= T * ay) return 2;
    return ((__float_as_int(gx) ^ __float_as_int(gy)) >= 0) ? 1 : 3;
}
// sqrt without MUFU: bit-hack rsqrt + 2 Newton iterations. x >= 1e-6 always.
__device__ __forceinline__ float fast_sqrt(float x) {
    float y = __int_as_float(0x5f3759df - (__float_as_int(x) >> 1));
    y = y * fmaf(-0.5f * x, y * y, 1.5f);
    y = y * fmaf(-0.5f * x, y * y, 1.5f);
    return x * y;
}
__device__ __forceinline__ float4 hblur4(float4 v0, float4 v1,
                                         float w0, float w1, float w2) {
    float4 o;
    o.x = w0 * (v0.x + v1.x) + w1 * (v0.y + v0.w) + w2 * v0.z;
    o.y = w0 * (v0.y + v1.y) + w1 * (v0.z + v1.x) + w2 * v0.w;
    o.z = w0 * (v0.z + v1.z) + w1 * (v0.w + v1.y) + w2 * v1.x;
    o.w = w0 * (v0.w + v1.w) + w1 * (v1.x + v1.z) + w2 * v1.y;
    return o;
}

struct Row6 { float m, x, y, z, w, p; };

__device__ __forceinline__ void sobel_row(const Row6& a, const Row6& b, const Row6& c,
                                          float4& mg, uchar4& cc) {
    {
        float gx = (a.y - a.m) + 2.0f * (b.y - b.m) + (c.y - c.m);
        float gy = (c.m - a.m) + 2.0f * (c.x - a.x) + (c.y - a.y);
        mg.x = fmaf(gx, gx, fmaf(gy, gy, 1e-6f)); cc.x = (unsigned char)octclass(gx, gy);
    }
    {
        float gx = (a.z - a.x) + 2.0f * (b.z - b.x) + (c.z - c.x);
        float gy = (c.x - a.x) + 2.0f * (c.y - a.y) + (c.z - a.z);
        mg.y = fmaf(gx, gx, fmaf(gy, gy, 1e-6f)); cc.y = (unsigned char)octclass(gx, gy);
    }
    {
        float gx = (a.w - a.y) + 2.0f * (b.w - b.y) + (c.w - c.y);
        float gy = (c.y - a.y) + 2.0f * (c.z - a.z) + (c.w - a.w);
        mg.z = fmaf(gx, gx, fmaf(gy, gy, 1e-6f)); cc.z = (unsigned char)octclass(gx, gy);
    }
    {
        float gx = (a.p - a.z) + 2.0f * (b.p - b.z) + (c.p - c.z);
        float gy = (c.z - a.z) + 2.0f * (c.w - a.w) + (c.p - a.p);
        mg.w = fmaf(gx, gx, fmaf(gy, gy, 1e-6f)); cc.w = (unsigned char)octclass(gx, gy);
    }
}

__global__ __launch_bounds__(NT)
void canny_fused_kernel(const float* __restrict__ in, float* __restrict__ out)
{
    // 64x32 output tile. Row stride 76 floats (rows 16B aligned).
    //  poolA: sg[40][76] (gray)  -> later smg[34][76] (squared mag, cols 1..66)
    //  poolB: th[40][76] (border-path hblur only)
    //  poolC: sb[36][76] (blurred, cols 0..67)
    __shared__ __align__(16) float poolA[40 * 76];
    __shared__ __align__(16) float poolB[40 * 76];
    __shared__ __align__(16) float poolC[36 * 76];
    __shared__ __align__(16) unsigned char sclbuf[34 * 76];

    float (*sg)[76]  = reinterpret_cast<float(*)[76]>(poolA);
    float (*smg)[76] = reinterpret_cast<float(*)[76]>(poolA);
    float (*th)[76]  = reinterpret_cast<float(*)[76]>(poolB);
    float (*sb)[76]  = reinterpret_cast<float(*)[76]>(poolC);
    unsigned char (*scl)[76] = reinterpret_cast<unsigned char(*)[76]>(sclbuf);

    const int tid = threadIdx.x;
    const int bx0 = blockIdx.x * 64, by0 = blockIdx.y * 32;
    const float* base = in + (size_t)blockIdx.z * 786432u;
    const float w0 = 0.054488685f, w1 = 0.24420134f, w2 = 0.40261995f;

    const bool reflX = (blockIdx.x == 0u) | (blockIdx.x == 7u);
    const bool reflY = (blockIdx.y == 0u) | (blockIdx.y == 15u);

    if (!(reflX | reflY)) {
        // ======== INTERIOR path: 3 barriers ========
        // ---- stage 1: gray, 20 row-pairs x 18 groups = 360 items ----
        #pragma unroll
        for (int k = 0; k < 2; k++) {
            int u = tid + k * NT;
            if (u < 360) {
                int pr = u / 18, g = u - pr * 18;
                int ly = 2 * pr;
                int off = (by0 - 4 + ly) * 512 + (bx0 - 4) + 4 * g;
                #pragma unroll
                for (int rr = 0; rr < 2; rr++) {
                    float4 r  = *(const float4*)(base + off);
                    float4 gg = *(const float4*)(base + off + 262144);
                    float4 bb = *(const float4*)(base + off + 524288);
                    float4 o;
                    o.x = fmaf(0.1495f, r.x, fmaf(0.2935f, gg.x, fmaf(0.057f, bb.x, 0.5f)));
                    o.y = fmaf(0.1495f, r.y, fmaf(0.2935f, gg.y, fmaf(0.057f, bb.y, 0.5f)));
                    o.z = fmaf(0.1495f, r.z, fmaf(0.2935f, gg.z, fmaf(0.057f, bb.z, 0.5f)));
                    o.w = fmaf(0.1495f, r.w, fmaf(0.2935f, gg.w, fmaf(0.057f, bb.w, 0.5f)));
                    *(float4*)&sg[ly + rr][4 * g] = o;
                    off += 512;
                }
            }
        }
        __syncthreads();

        // ---- merged blur (hblur in regs + vblur) -> sb rows 0..35; 18 pairs x 18 = 324 ----
        #pragma unroll
        for (int k = 0; k < 2; k++) {
            int u = tid + k * NT;
            if (u < 324) {
                int pr = u / 18, g = u - pr * 18;
                int i = 2 * pr;
                float4 acc0 = make_float4(0.f, 0.f, 0.f, 0.f);
                float4 acc1 = make_float4(0.f, 0.f, 0.f, 0.f);
                const float wv0[6] = {w0, w1, w2, w1, w0, 0.f};
                const float wv1[6] = {0.f, w0, w1, w2, w1, w0};
                #pragma unroll
                for (int rr = 0; rr < 6; rr++) {
                    float4 a = *(const float4*)&sg[i + rr][4 * g];
                    float4 b = *(const float4*)&sg[i + rr][4 * g + 4];
                    float4 hb = hblur4(a, b, w0, w1, w2);
                    float wa = wv0[rr], wb = wv1[rr];
                    if (rr < 5) {
                        acc0.x = fmaf(wa, hb.x, acc0.x); acc0.y = fmaf(wa, hb.y, acc0.y);
                        acc0.z = fmaf(wa, hb.z, acc0.z); acc0.w = fmaf(wa, hb.w, acc0.w);
                    }
                    if (rr > 0) {
                        acc1.x = fmaf(wb, hb.x, acc1.x); acc1.y = fmaf(wb, hb.y, acc1.y);
                        acc1.z = fmaf(wb, hb.z, acc1.z); acc1.w = fmaf(wb, hb.w, acc1.w);
                    }
                }
                *(float4*)&sb[i][4 * g]     = acc0;
                *(float4*)&sb[i + 1][4 * g] = acc1;
            }
        }
    } else {
        // ======== BORDER path: classic 5 stages (4 barriers) ========
        for (int u = tid; u < 40 * 72; u += NT) {
            int ly = u / 72, lx = u - ly * 72;
            int ay = by0 - 4 + ly, ax = bx0 - 4 + lx;
            float g = 0.0f;
            if ((unsigned)ay < 512u && (unsigned)ax < 512u) g = grayf(base, ay * 512 + ax);
            sg[ly][lx] = g;
        }
        __syncthreads();

        // hblur with reflect-x (or fast if !reflX)
        if (!reflX) {
            #pragma unroll
            for (int k = 0; k < 2; k++) {
                int u = tid + k * NT;
                if (u < 360) {
                    int pr = u / 18, g = u - pr * 18;
                    int ly = 2 * pr;
                    float4 a0 = *(const float4*)&sg[ly][4 * g];
                    float4 a1 = *(const float4*)&sg[ly][4 * g + 4];
                    float4 b0 = *(const float4*)&sg[ly + 1][4 * g];
                    float4 b1 = *(const float4*)&sg[ly + 1][4 * g + 4];
                    *(float4*)&th[ly][4 * g]     = hblur4(a0, a1, w0, w1, w2);
                    *(float4*)&th[ly + 1][4 * g] = hblur4(b0, b1, w0, w1, w2);
                }
            }
        } else {
            const int ox = bx0 - 4;
            for (int u = tid; u < 40 * 68; u += NT) {
                int ly = u / 68, j = u - ly * 68;
                int cx = clamp511(bx0 - 2 + j);
                th[ly][j] = w0 * (sg[ly][reflect512(cx - 2) - ox] + sg[ly][reflect512(cx + 2) - ox])
                          + w1 * (sg[ly][reflect512(cx - 1) - ox] + sg[ly][reflect512(cx + 1) - ox])
                          + w2 * sg[ly][reflect512(cx) - ox];
            }
        }
        __syncthreads();

        // vblur with reflect-y
        #pragma unroll
        for (int k = 0; k < 2; k++) {
            int u = tid + k * NT;
            if (u < 324) {
                int pr = u / 18, g = u - pr * 18;
                int i = 2 * pr;
                #pragma unroll
                for (int rr = 0; rr < 2; rr++) {
                    int ir = i + rr;
                    int r0, r1, r2, r3, r4;
                    if (!reflY) { r0 = ir; r1 = ir + 1; r2 = ir + 2; r3 = ir + 3; r4 = ir + 4; }
                    else {
                        int cy = clamp511(by0 - 2 + ir), oy = by0 - 4;
                        r0 = reflect512(cy - 2) - oy; r1 = reflect512(cy - 1) - oy;
                        r2 = reflect512(cy) - oy;
                        r3 = reflect512(cy + 1) - oy; r4 = reflect512(cy + 2) - oy;
                    }
                    float4 a = *(const float4*)&th[r0][4 * g];
                    float4 b = *(const float4*)&th[r1][4 * g];
                    float4 c = *(const float4*)&th[r2][4 * g];
                    float4 d = *(const float4*)&th[r3][4 * g];
                    float4 e = *(const float4*)&th[r4][4 * g];
                    float4 o;
                    o.x = w0 * (a.x + e.x) + w1 * (b.x + d.x) + w2 * c.x;
                    o.y = w0 * (a.y + e.y) + w1 * (b.y + d.y) + w2 * c.y;
                    o.z = w0 * (a.z + e.z) + w1 * (b.z + d.z) + w2 * c.z;
                    o.w = w0 * (a.w + e.w) + w1 * (b.w + d.w) + w2 * c.w;
                    *(float4*)&sb[ir][4 * g] = o;
                }
            }
        }
    }
    __syncthreads();

    // ---- Sobel + squared mag + class -> smg (aliases sg; gray dead); 17 pairs x 18 = 306 ----
    #pragma unroll
    for (int k = 0; k < 2; k++) {
        int u = tid + k * NT;
        if (u < 306) {
            int pr = u / 18, g = u - pr * 18;
            int i = 2 * pr;
            int cm = max(4 * g - 1, 0);
            Row6 r[4];
            #pragma unroll
            for (int rr = 0; rr < 4; rr++) {
                const float* row = &sb[i + rr][0];
                float4 v = *(const float4*)&row[4 * g];
                r[rr].m = row[cm]; r[rr].x = v.x; r[rr].y = v.y;
                r[rr].z = v.z;     r[rr].w = v.w; r[rr].p = row[4 * g + 4];
            }
            float4 mgA, mgB; uchar4 ccA, ccB;
            sobel_row(r[0], r[1], r[2], mgA, ccA);
            sobel_row(r[1], r[2], r[3], mgB, ccB);
            *(float4*)&smg[i][4 * g]     = mgA;
            *(uchar4*)&scl[i][4 * g]     = ccA;
            *(float4*)&smg[i + 1][4 * g] = mgB;
            *(uchar4*)&scl[i + 1][4 * g] = ccB;
        }
    }
    __syncthreads();

    // ---- NMS on squared magnitudes + fast_sqrt; 512 items ----
    const unsigned DY = 0x0001u, DX = 0x0122u;
    const bool border = reflX | reflY;

    #pragma unroll
    for (int k = 0; k < 2; k++) {
        int u = tid + k * NT;
        int iy = u >> 4, g = u & 15;
        int ii = iy + 1;
        int j0 = 4 * g + 2;

        float2 ca = *(const float2*)&smg[ii][j0];
        float2 cb = *(const float2*)&smg[ii][j0 + 2];
        uchar2 ka = *(const uchar2*)&scl[ii][j0];
        uchar2 kb = *(const uchar2*)&scl[ii][j0 + 2];
        float mcv[4] = {ca.x, ca.y, cb.x, cb.y};
        int   cls[4] = {ka.x, ka.y, kb.x, kb.y};

        float4 res;
        float* rp = &res.x;
        #pragma unroll
        for (int t = 0; t < 4; t++) {
            int s  = cls[t] * 4;
            int dy = (int)((DY >> s) & 0xFu) - 1;
            int dx = (int)((DX >> s) & 0xFu) - 1;
            int jj = j0 + t;
            float mp = smg[ii + dy][jj + dx];
            float mq = smg[ii - dy][jj - dx];
            if (border) {
                int ay = by0 + iy, ax = bx0 + 4 * g + t;
                if (!((unsigned)(ay + dy) < 512u && (unsigned)(ax + dx) < 512u)) mp = 0.0f;
                if (!((unsigned)(ay - dy) < 512u && (unsigned)(ax - dx) < 512u)) mq = 0.0f;
            }
            float m = mcv[t];
            rp[t] = (m > mp && m > mq) ? fast_sqrt(m) : 0.0f;
        }
        *(float4*)&out[((size_t)blockIdx.z * 512 + by0 + iy) * 512 + bx0 + 4 * g] = res;
    }
}

extern "C" void kernel_launch(void* const* d_in, const int* in_sizes, int n_in,
                              void* d_out, int out_size)
{
    (void)in_sizes; (void)n_in; (void)out_size;
    const float* data = (const float*)d_in[0];
    float* out = (float*)d_out;

    dim3 grid(8, 16, 16);
    dim3 block(NT);
    canny_fused_kernel<<<grid, block>>>(data, out);
}